// round 9
// baseline (speedup 1.0000x reference)
#include <cuda_runtime.h>
#include <cuda_bf16.h>

// CenterLossLayer: B=16384, C=1024, D=512, alpha=0.5
//   result[b]   = sum_d (features[b,d] - centers[labels[b],d])^2
//   delta[c,d]  = sum_{b: labels[b]==c} (centers[c,d] - features[b,d])
//   new_centers = centers - alpha * delta / (count_c + 1)
// d_out: [0..B) result f32 ; [B .. B+C*D) new_centers f32
//
// Single launch. Grid=296 (2 blocks/SM), 384 threads (12 warps) -> 24 warps/SM.
// Centers read from smem (not registers) to keep regs <= 85 for 2-block residency.

#define BATCH       16384
#define NUM_CLASSES 1024
#define FEAT_DIM    512
#define ALPHA       0.5f

#define NBLK     296
#define THREADS  384
#define NWARPS   (THREADS / 32)    // 12
#define GMAX     4                 // max classes per block (ceil(1024/296)=4)
#define CAPG     96                // per-class capacity (E=16, max ~40)
#define NF4      (FEAT_DIM / 4)    // 128

#define F4_ZERO make_float4(0.f, 0.f, 0.f, 0.f)

__device__ __forceinline__ float4 f4_sub(float4 a, float4 b) {
    return make_float4(a.x - b.x, a.y - b.y, a.z - b.z, a.w - b.w);
}
__device__ __forceinline__ void f4_acc(float4& a, float4 b) {
    a.x += b.x; a.y += b.y; a.z += b.z; a.w += b.w;
}
__device__ __forceinline__ float f4_dot(float4 a) {
    return a.x * a.x + a.y * a.y + a.z * a.z + a.w * a.w;
}

__global__ __launch_bounds__(THREADS, 2)
void center_loss_kernel(const float* __restrict__ features,
                        const float* __restrict__ centers,
                        const int*   __restrict__ labels,
                        float*       __restrict__ out_result,
                        float*       __restrict__ out_centers) {
    __shared__ __align__(16) float s_centers[GMAX * FEAT_DIM];   // 8 KB
    __shared__ __align__(16) float s_delta[GMAX * FEAT_DIM];     // 8 KB
    __shared__ int s_list[GMAX][CAPG];                           // 1.5 KB
    __shared__ int s_gcnt[GMAX];

    const int t   = threadIdx.x;
    const int bid = blockIdx.x;
    const int lo  = (bid * NUM_CLASSES) / NBLK;
    const int hi  = ((bid + 1) * NUM_CLASSES) / NBLK;
    const int nc  = hi - lo;                                     // 3 or 4

    if (t < GMAX) s_gcnt[t] = 0;
    {
        const float4* src = reinterpret_cast<const float4*>(centers + (size_t)lo * FEAT_DIM);
        float4* dst = reinterpret_cast<float4*>(s_centers);
        float4* dz  = reinterpret_cast<float4*>(s_delta);
        #pragma unroll
        for (int k = 0; k < 2; k++) {
            int idx = k * THREADS + t;                           // 0..767
            if (idx < nc * NF4) { dst[idx] = src[idx]; dz[idx] = F4_ZERO; }
        }
    }
    __syncthreads();

    // ---- scan labels once per block (64 KB, L2-resident chip-wide) ----
    const int4* lab4 = reinterpret_cast<const int4*>(labels);
    for (int idx4 = t; idx4 < BATCH / 4; idx4 += THREADS) {      // ~10.7 iters
        int4 L = lab4[idx4];
        int b0 = idx4 * 4;
        int ls[4] = {L.x, L.y, L.z, L.w};
        #pragma unroll
        for (int j = 0; j < 4; j++) {
            int g = ls[j] - lo;
            if ((unsigned)g < (unsigned)nc) {
                int pos = atomicAdd(&s_gcnt[g], 1);
                if (pos < CAPG) s_list[g][pos] = b0 + j;
            }
        }
    }
    __syncthreads();

    // ---- flat ordering over the block's samples; warp takes a chunk ----
    const int cnt0 = min(s_gcnt[0], CAPG);
    const int cnt1 = (nc > 1) ? min(s_gcnt[1], CAPG) : 0;
    const int cnt2 = (nc > 2) ? min(s_gcnt[2], CAPG) : 0;
    const int cnt3 = (nc > 3) ? min(s_gcnt[3], CAPG) : 0;
    const int o1 = cnt0, o2 = o1 + cnt1, o3 = o2 + cnt2;
    const int total = o3 + cnt3;

    const int warp = t >> 5;
    const int lane = t & 31;
    const int js = (total * warp) / NWARPS;
    const int je = (total * (warp + 1)) / NWARPS;

    float4 a0 = F4_ZERO, a1 = F4_ZERO, a2 = F4_ZERO, a3 = F4_ZERO;
    float4 f0, f1, f2, f3;

    int j = js, g_cur = -1, b_cur = -1;
    if (j < je) {
        int base;
        if      (j < o1) { g_cur = 0; base = 0;  }
        else if (j < o2) { g_cur = 1; base = o1; }
        else if (j < o3) { g_cur = 2; base = o2; }
        else             { g_cur = 3; base = o3; }
        b_cur = s_list[g_cur][j - base];
        const float4* fr = reinterpret_cast<const float4*>(features + (size_t)b_cur * FEAT_DIM);
        f0 = fr[lane]; f1 = fr[lane + 32]; f2 = fr[lane + 64]; f3 = fr[lane + 96];
    }

    while (j < je) {
        // prefetch next sample (overlaps current compute)
        int jn = j + 1, g_next = -1, b_next = -1;
        float4 n0, n1, n2, n3;
        if (jn < je) {
            int base;
            if      (jn < o1) { g_next = 0; base = 0;  }
            else if (jn < o2) { g_next = 1; base = o1; }
            else if (jn < o3) { g_next = 2; base = o2; }
            else              { g_next = 3; base = o3; }
            b_next = s_list[g_next][jn - base];
            const float4* fr = reinterpret_cast<const float4*>(features + (size_t)b_next * FEAT_DIM);
            n0 = fr[lane]; n1 = fr[lane + 32]; n2 = fr[lane + 64]; n3 = fr[lane + 96];
        }

        // process current sample (centers from smem — overlaps global wait)
        const float4* cen = reinterpret_cast<const float4*>(s_centers + g_cur * FEAT_DIM);
        float4 d0 = f4_sub(cen[lane],      f0);
        float4 d1 = f4_sub(cen[lane + 32], f1);
        float4 d2 = f4_sub(cen[lane + 64], f2);
        float4 d3 = f4_sub(cen[lane + 96], f3);
        f4_acc(a0, d0); f4_acc(a1, d1); f4_acc(a2, d2); f4_acc(a3, d3);
        float sq = f4_dot(d0) + f4_dot(d1) + f4_dot(d2) + f4_dot(d3);

        #pragma unroll
        for (int off = 16; off > 0; off >>= 1)
            sq += __shfl_xor_sync(0xFFFFFFFFu, sq, off);
        if (lane == 0) out_result[b_cur] = sq;

        // flush accumulator on class transition / chunk end (warp-uniform)
        if (g_next != g_cur) {
            float* dst = s_delta + g_cur * FEAT_DIM;
            atomicAdd(dst + 4 * lane + 0,        a0.x);
            atomicAdd(dst + 4 * lane + 1,        a0.y);
            atomicAdd(dst + 4 * lane + 2,        a0.z);
            atomicAdd(dst + 4 * lane + 3,        a0.w);
            atomicAdd(dst + 4 * (lane + 32) + 0, a1.x);
            atomicAdd(dst + 4 * (lane + 32) + 1, a1.y);
            atomicAdd(dst + 4 * (lane + 32) + 2, a1.z);
            atomicAdd(dst + 4 * (lane + 32) + 3, a1.w);
            atomicAdd(dst + 4 * (lane + 64) + 0, a2.x);
            atomicAdd(dst + 4 * (lane + 64) + 1, a2.y);
            atomicAdd(dst + 4 * (lane + 64) + 2, a2.z);
            atomicAdd(dst + 4 * (lane + 64) + 3, a2.w);
            atomicAdd(dst + 4 * (lane + 96) + 0, a3.x);
            atomicAdd(dst + 4 * (lane + 96) + 1, a3.y);
            atomicAdd(dst + 4 * (lane + 96) + 2, a3.z);
            atomicAdd(dst + 4 * (lane + 96) + 3, a3.w);
            a0 = F4_ZERO; a1 = F4_ZERO; a2 = F4_ZERO; a3 = F4_ZERO;
        }

        f0 = n0; f1 = n1; f2 = n2; f3 = n3;
        b_cur = b_next; g_cur = g_next; j = jn;
    }
    __syncthreads();

    // ---- finalize: new_centers = centers - alpha * delta / (count + 1) ----
    #pragma unroll
    for (int k = 0; k < 2; k++) {
        int idx = k * THREADS + t;                 // 0..767
        int gg  = idx / NF4;
        if (idx < nc * NF4) {
            float s = ALPHA / (float)(s_gcnt[gg] + 1);
            float4 de = reinterpret_cast<const float4*>(s_delta)[idx];
            float4 ce = reinterpret_cast<const float4*>(s_centers)[idx];
            float4 o;
            o.x = ce.x - s * de.x;
            o.y = ce.y - s * de.y;
            o.z = ce.z - s * de.z;
            o.w = ce.w - s * de.w;
            reinterpret_cast<float4*>(out_centers + (size_t)lo * FEAT_DIM)[idx] = o;
        }
    }
}

// ---------------------------------------------------------------------------
extern "C" void kernel_launch(void* const* d_in, const int* in_sizes, int n_in,
                              void* d_out, int out_size) {
    const float* features = (const float*)d_in[0];
    const float* centers  = (const float*)d_in[1];
    const int*   labels   = (const int*)d_in[2];

    float* out_result      = (float*)d_out;          // [BATCH]
    float* out_new_centers = (float*)d_out + BATCH;  // [NUM_CLASSES * FEAT_DIM]

    center_loss_kernel<<<NBLK, THREADS>>>(
        features, centers, labels, out_result, out_new_centers);
}

// round 10
// speedup vs baseline: 1.7402x; 1.7402x over previous
#include <cuda_runtime.h>
#include <cuda_bf16.h>

// CenterLossLayer: B=16384, C=1024, D=512, alpha=0.5
//   result[b]   = sum_d (features[b,d] - centers[labels[b],d])^2
//   delta[c,d]  = sum_{b: labels[b]==c} (centers[c,d] - features[b,d])
//   new_centers = centers - alpha * delta / (count_c + 1)
// d_out: [0..B) result f32 ; [B .. B+C*D) new_centers f32
//
// Single launch, G=4 classes/block, register-cached centers (R6 base).
// Hot loop processes 4 samples per batch: 16 LDG.128 issued back-to-back
// (8KB in flight per warp) before any compute -> 4x memory parallelism.

#define BATCH       16384
#define NUM_CLASSES 1024
#define FEAT_DIM    512
#define ALPHA       0.5f

#define G        4                 // classes per block
#define THREADS  256
#define NWARPS   (THREADS / 32)    // 8
#define NREP     (NWARPS / G)      // 2 replica warps per class
#define CAPG     64                // per-class list capacity (E=16, max ~40)
#define NF4      (FEAT_DIM / 4)    // 128 float4 per row

#define F4_ZERO make_float4(0.f, 0.f, 0.f, 0.f)

__device__ __forceinline__ float4 f4_sub(float4 a, float4 b) {
    return make_float4(a.x - b.x, a.y - b.y, a.z - b.z, a.w - b.w);
}
__device__ __forceinline__ void f4_acc(float4& a, float4 b) {
    a.x += b.x; a.y += b.y; a.z += b.z; a.w += b.w;
}
__device__ __forceinline__ float f4_dot(float4 a) {
    return a.x * a.x + a.y * a.y + a.z * a.z + a.w * a.w;
}

__global__ __launch_bounds__(THREADS, 2)
void center_loss_fused_kernel(const float* __restrict__ features,
                              const float* __restrict__ centers,
                              const int*   __restrict__ labels,
                              float*       __restrict__ out_result,
                              float*       __restrict__ out_centers) {
    __shared__ __align__(16) float s_centers[G * FEAT_DIM];          // 8 KB
    __shared__ __align__(16) float s_delta[G * NREP * FEAT_DIM];     // 16 KB
    __shared__ int s_list[G][CAPG];                                  // 1 KB
    __shared__ int s_gcnt[G];

    const int t  = threadIdx.x;
    const int c0 = blockIdx.x * G;

    if (t < G) s_gcnt[t] = 0;
    {   // load G center rows: 512 float4s, 256 threads -> 2 each
        const float4* src = reinterpret_cast<const float4*>(centers + (size_t)c0 * FEAT_DIM);
        float4* dst = reinterpret_cast<float4*>(s_centers);
        dst[t]           = src[t];
        dst[t + THREADS] = src[t + THREADS];
    }
    __syncthreads();

    // ---- scan labels once per block (64 KB, L2-resident chip-wide) ----
    const int4* lab4 = reinterpret_cast<const int4*>(labels);
    #pragma unroll
    for (int i = 0; i < BATCH / 4 / THREADS; i++) {        // 16 iterations
        int idx4 = i * THREADS + t;                        // coalesced
        int4 L = lab4[idx4];
        int b0 = idx4 * 4;
        int ls[4] = {L.x, L.y, L.z, L.w};
        #pragma unroll
        for (int j = 0; j < 4; j++) {
            int g = ls[j] - c0;
            if ((unsigned)g < (unsigned)G) {
                int pos = atomicAdd(&s_gcnt[g], 1);
                if (pos < CAPG) s_list[g][pos] = b0 + j;
            }
        }
    }
    __syncthreads();

    // ---- warp-per-class (2 replicas), batch-4 register pipeline ----
    const int warp = t >> 5;
    const int lane = t & 31;
    const int g    = warp & (G - 1);
    const int r    = warp >> 2;                // replica id 0..NREP-1
    const int cnt  = min(s_gcnt[g], CAPG);

    // center row cached in registers (this lane's 16 floats)
    const float4* cen4 = reinterpret_cast<const float4*>(s_centers + g * FEAT_DIM);
    const float4 c0v = cen4[lane +  0];
    const float4 c1v = cen4[lane + 32];
    const float4 c2v = cen4[lane + 64];
    const float4 c3v = cen4[lane + 96];

    float4 a0 = F4_ZERO, a1 = F4_ZERO, a2 = F4_ZERO, a3 = F4_ZERO;

    for (int i0 = r; i0 < cnt; i0 += 4 * NREP) {
        // gather up to 4 sample indices (warp-uniform)
        int b[4];
        #pragma unroll
        for (int k = 0; k < 4; k++) {
            int idx = i0 + k * NREP;
            b[k] = (idx < cnt) ? s_list[g][idx] : -1;
        }

        // issue ALL loads first: up to 16 LDG.128 in flight (8 KB/warp)
        float4 f[4][4];
        #pragma unroll
        for (int k = 0; k < 4; k++) {
            if (b[k] >= 0) {
                const float4* fr = reinterpret_cast<const float4*>(
                    features + (size_t)b[k] * FEAT_DIM);
                f[k][0] = fr[lane];
                f[k][1] = fr[lane + 32];
                f[k][2] = fr[lane + 64];
                f[k][3] = fr[lane + 96];
            }
        }

        // compute all 4 (independent chains)
        float sq[4];
        #pragma unroll
        for (int k = 0; k < 4; k++) {
            if (b[k] >= 0) {
                float4 d0 = f4_sub(c0v, f[k][0]);
                float4 d1 = f4_sub(c1v, f[k][1]);
                float4 d2 = f4_sub(c2v, f[k][2]);
                float4 d3 = f4_sub(c3v, f[k][3]);
                f4_acc(a0, d0); f4_acc(a1, d1); f4_acc(a2, d2); f4_acc(a3, d3);
                sq[k] = f4_dot(d0) + f4_dot(d1) + f4_dot(d2) + f4_dot(d3);
            } else {
                sq[k] = 0.0f;
            }
        }

        // 4 interleaved butterfly reductions (chains overlap)
        #pragma unroll
        for (int off = 16; off > 0; off >>= 1) {
            sq[0] += __shfl_xor_sync(0xFFFFFFFFu, sq[0], off);
            sq[1] += __shfl_xor_sync(0xFFFFFFFFu, sq[1], off);
            sq[2] += __shfl_xor_sync(0xFFFFFFFFu, sq[2], off);
            sq[3] += __shfl_xor_sync(0xFFFFFFFFu, sq[3], off);
        }
        if (lane == 0) {
            #pragma unroll
            for (int k = 0; k < 4; k++)
                if (b[k] >= 0) out_result[b[k]] = sq[k];
        }
    }

    // write replica accumulator (plain STS, full coverage — no init needed)
    float4* dd = reinterpret_cast<float4*>(s_delta + (size_t)(g * NREP + r) * FEAT_DIM);
    dd[lane] = a0; dd[lane + 32] = a1; dd[lane + 64] = a2; dd[lane + 96] = a3;
    __syncthreads();

    // ---- finalize: reduce 2 replicas; new_centers = centers - a*delta/(cnt+1)
    #pragma unroll
    for (int k = 0; k < 2; k++) {
        int idx = k * THREADS + t;         // 0..511
        int gg  = idx / NF4;               // class within group
        int q   = idx % NF4;
        float s = ALPHA / (float)(s_gcnt[gg] + 1);

        const float4* base = reinterpret_cast<const float4*>(s_delta);
        float4 acc = base[(gg * NREP + 0) * NF4 + q];
        f4_acc(acc, base[(gg * NREP + 1) * NF4 + q]);

        float4 ce = reinterpret_cast<const float4*>(s_centers)[idx];
        float4 o;
        o.x = ce.x - s * acc.x;
        o.y = ce.y - s * acc.y;
        o.z = ce.z - s * acc.z;
        o.w = ce.w - s * acc.w;
        reinterpret_cast<float4*>(out_centers + (size_t)c0 * FEAT_DIM)[idx] = o;
    }
}

// ---------------------------------------------------------------------------
extern "C" void kernel_launch(void* const* d_in, const int* in_sizes, int n_in,
                              void* d_out, int out_size) {
    const float* features = (const float*)d_in[0];
    const float* centers  = (const float*)d_in[1];
    const int*   labels   = (const int*)d_in[2];

    float* out_result      = (float*)d_out;          // [BATCH]
    float* out_new_centers = (float*)d_out + BATCH;  // [NUM_CLASSES * FEAT_DIM]

    center_loss_fused_kernel<<<NUM_CLASSES / G, THREADS>>>(
        features, centers, labels, out_result, out_new_centers);
}